// round 2
// baseline (speedup 1.0000x reference)
#include <cuda_runtime.h>

#define BATCH 32
#define NCH   4
#define HH    512
#define WW    512
#define PLANE (HH*WW)          /* 262144 */
#define NSTEPS 8
#define D_SCALE 0.2f
#define RHO_SCALE 0.1f

// Ping-pong scratch for the evolving channel-0 field (2 x 32 MiB).
__device__ float g_buf0[BATCH * PLANE];
__device__ float g_buf1[BATCH * PLANE];
// Per-step channel-0 sums: slot s = sum of field entering step s.
__device__ float g_sum0[(NSTEPS + 1) * BATCH];
// Constant sums of channels 1..3 (index (c-1)*BATCH + b).
__device__ float g_sumc[3 * BATCH];

__global__ void zero_sums_kernel() {
    int i = threadIdx.x;
    if (i < (NSTEPS + 1) * BATCH) g_sum0[i] = 0.0f;
    if (i < 3 * BATCH)            g_sumc[i] = 0.0f;
}

// Copy channels 1..3 input->output, reduce per-(batch,channel) sums.
// grid = (PLANE/4/256, BATCH*NCH), block = 256. Each thread: one float4.
__global__ void init_kernel(const float* __restrict__ x, float* __restrict__ out) {
    const int p = blockIdx.y;            // plane id = b*4 + c
    const int b = p >> 2;
    const int c = p & 3;
    const int i = blockIdx.x * blockDim.x + threadIdx.x;   // 0..65535

    const float4* src = (const float4*)(x + (size_t)p * PLANE);
    float4 v = src[i];
    if (c != 0) {
        ((float4*)(out + (size_t)p * PLANE))[i] = v;
    }
    float s = v.x + v.y + v.z + v.w;

    // warp reduce
    #pragma unroll
    for (int o = 16; o > 0; o >>= 1) s += __shfl_down_sync(0xffffffffu, s, o);
    __shared__ float ws[8];
    const int lane = threadIdx.x & 31;
    const int w    = threadIdx.x >> 5;
    if (lane == 0) ws[w] = s;
    __syncthreads();
    if (w == 0) {
        s = (lane < 8) ? ws[lane] : 0.0f;
        #pragma unroll
        for (int o = 4; o > 0; o >>= 1) s += __shfl_down_sync(0x000000ffu, s, o);
        if (lane == 0) {
            if (c == 0) atomicAdd(&g_sum0[0 * BATCH + b], s);
            else        atomicAdd(&g_sumc[(c - 1) * BATCH + b], s);
        }
    }
}

// One reaction-diffusion step on channel 0 for all batches.
// grid = (PLANE/4/256, BATCH), block = 256. Each thread: 4 consecutive x.
__global__ void step_kernel(const float* __restrict__ src, int src_bstride,
                            float* __restrict__ dst, int dst_bstride,
                            const float* __restrict__ Wm,
                            const float* __restrict__ bias,
                            const int* __restrict__ t, int step) {
    const int b = blockIdx.y;

    // --- Derive D, rho from previous-step sums (redundant per thread, trivial cost) ---
    const float inv = 1.0f / (float)PLANE;
    const float f0 = g_sum0[step * BATCH + b] * inv;
    const float f1 = g_sumc[0 * BATCH + b] * inv;
    const float f2 = g_sumc[1 * BATCH + b] * inv;
    const float f3 = g_sumc[2 * BATCH + b] * inv;
    // W is row-major (4,2)
    const float z0 = f0 * Wm[0] + f1 * Wm[2] + f2 * Wm[4] + f3 * Wm[6] + bias[0];
    const float z1 = f0 * Wm[1] + f1 * Wm[3] + f2 * Wm[5] + f3 * Wm[7] + bias[1];
    float D   = D_SCALE   / (1.0f + expf(-z0));
    float rho = RHO_SCALE / (1.0f + expf(-z1));
    if (t[b] <= step) { D = 0.0f; rho = 0.0f; }   // mask off -> exact identity

    const float* __restrict__ u = src + (size_t)b * src_bstride;
    float* __restrict__ v       = dst + (size_t)b * dst_bstride;

    const int tid = blockIdx.x * blockDim.x + threadIdx.x;  // 0..65535
    const int x4  = tid << 2;                               // element index
    const int y   = x4 >> 9;
    const int xx  = x4 & 511;
    const int row = y << 9;
    const int rym = ((y + 511) & 511) << 9;
    const int ryp = ((y + 1) & 511) << 9;

    const float4 cc = *(const float4*)(u + row + xx);
    const float4 up = *(const float4*)(u + rym + xx);
    const float4 dn = *(const float4*)(u + ryp + xx);
    const float left  = u[row + ((xx + 511) & 511)];
    const float right = u[row + ((xx + 4) & 511)];

    float4 r;
    r.x = cc.x + D * (up.x + dn.x + left + cc.y - 4.0f * cc.x) + rho * cc.x * (1.0f - cc.x);
    r.y = cc.y + D * (up.y + dn.y + cc.x + cc.z - 4.0f * cc.y) + rho * cc.y * (1.0f - cc.y);
    r.z = cc.z + D * (up.z + dn.z + cc.y + cc.w - 4.0f * cc.z) + rho * cc.z * (1.0f - cc.z);
    r.w = cc.w + D * (up.w + dn.w + cc.z + right - 4.0f * cc.w) + rho * cc.w * (1.0f - cc.w);

    *(float4*)(v + row + xx) = r;

    // --- Reduce sum of updated field for next step's features ---
    float s = r.x + r.y + r.z + r.w;
    #pragma unroll
    for (int o = 16; o > 0; o >>= 1) s += __shfl_down_sync(0xffffffffu, s, o);
    __shared__ float ws[8];
    const int lane = threadIdx.x & 31;
    const int w    = threadIdx.x >> 5;
    if (lane == 0) ws[w] = s;
    __syncthreads();
    if (w == 0) {
        s = (lane < 8) ? ws[lane] : 0.0f;
        #pragma unroll
        for (int o = 4; o > 0; o >>= 1) s += __shfl_down_sync(0x000000ffu, s, o);
        if (lane == 0) atomicAdd(&g_sum0[(step + 1) * BATCH + b], s);
    }
}

extern "C" void kernel_launch(void* const* d_in, const int* in_sizes, int n_in,
                              void* d_out, int out_size) {
    const float* x  = (const float*)d_in[0];   // (32,4,512,512)
    const float* Wm = (const float*)d_in[1];   // (4,2)
    const float* bb = (const float*)d_in[2];   // (2,)
    const int*   t  = (const int*)d_in[3];     // (32,)
    float* out = (float*)d_out;

    const dim3 blk(256);

    zero_sums_kernel<<<1, 320>>>();

    // Copy ch1..3, reduce all per-(b,c) sums.
    init_kernel<<<dim3(PLANE / 4 / 256, BATCH * NCH), blk>>>(x, out);

    float* bufA; float* bufB;
    cudaGetSymbolAddress((void**)&bufA, g_buf0);
    cudaGetSymbolAddress((void**)&bufB, g_buf1);

    const dim3 sgrid(PLANE / 4 / 256, BATCH);
    for (int s = 0; s < NSTEPS; s++) {
        const float* src;  int sstride;
        float*       dst;  int dstride;
        if (s == 0) { src = x;  sstride = NCH * PLANE; }           // input ch0
        else        { src = ((s - 1) & 1) ? bufB : bufA; sstride = PLANE; }
        if (s == NSTEPS - 1) { dst = out; dstride = NCH * PLANE; } // output ch0
        else                 { dst = (s & 1) ? bufB : bufA; dstride = PLANE; }
        step_kernel<<<sgrid, blk>>>(src, sstride, dst, dstride, Wm, bb, t, s);
    }
}

// round 3
// speedup vs baseline: 1.0146x; 1.0146x over previous
#include <cuda_runtime.h>

#define BATCH 32
#define NCH   4
#define HH    512
#define WW    512
#define PLANE (HH*WW)          /* 262144 */
#define NSTEPS 8
#define D_SCALE 0.2f
#define RHO_SCALE 0.1f
#define ROWS_PER_WARP 8
#define WARPS_PER_BLK 4

// Ping-pong scratch for the evolving channel-0 field (2 x 32 MiB).
__device__ float g_buf0[BATCH * PLANE];
__device__ float g_buf1[BATCH * PLANE];
// Per-step channel-0 sums: slot s = sum of field entering step s.
__device__ float g_sum0[(NSTEPS + 1) * BATCH];
// Constant sums of channels 1..3 (index (c-1)*BATCH + b).
__device__ float g_sumc[3 * BATCH];

__global__ void zero_sums_kernel() {
    int i = threadIdx.x;
    if (i < (NSTEPS + 1) * BATCH) g_sum0[i] = 0.0f;
    if (i < 3 * BATCH)            g_sumc[i] = 0.0f;
}

// Copy channels 1..3 input->output, reduce per-(batch,channel) sums.
// grid = (PLANE/4/256, BATCH*NCH), block = 256. Each thread: one float4.
__global__ void init_kernel(const float* __restrict__ x, float* __restrict__ out) {
    const int p = blockIdx.y;            // plane id = b*4 + c
    const int b = p >> 2;
    const int c = p & 3;
    const int i = blockIdx.x * blockDim.x + threadIdx.x;   // 0..65535

    const float4* src = (const float4*)(x + (size_t)p * PLANE);
    float4 v = src[i];
    if (c != 0) {
        ((float4*)(out + (size_t)p * PLANE))[i] = v;
    }
    float s = v.x + v.y + v.z + v.w;

    #pragma unroll
    for (int o = 16; o > 0; o >>= 1) s += __shfl_down_sync(0xffffffffu, s, o);
    __shared__ float ws[8];
    const int lane = threadIdx.x & 31;
    const int w    = threadIdx.x >> 5;
    if (lane == 0) ws[w] = s;
    __syncthreads();
    if (w == 0) {
        s = (lane < 8) ? ws[lane] : 0.0f;
        #pragma unroll
        for (int o = 4; o > 0; o >>= 1) s += __shfl_down_sync(0x000000ffu, s, o);
        if (lane == 0) {
            if (c == 0) atomicAdd(&g_sum0[0 * BATCH + b], s);
            else        atomicAdd(&g_sumc[(c - 1) * BATCH + b], s);
        }
    }
}

__device__ __forceinline__ void load_row16(float* d, const float* __restrict__ p) {
    float4 a = ((const float4*)p)[0];
    float4 b = ((const float4*)p)[1];
    float4 c = ((const float4*)p)[2];
    float4 e = ((const float4*)p)[3];
    d[0]=a.x; d[1]=a.y; d[2]=a.z; d[3]=a.w;
    d[4]=b.x; d[5]=b.y; d[6]=b.z; d[7]=b.w;
    d[8]=c.x; d[9]=c.y; d[10]=c.z; d[11]=c.w;
    d[12]=e.x; d[13]=e.y; d[14]=e.z; d[15]=e.w;
}

// One reaction-diffusion step on channel 0 for all batches.
// Warp-per-row: lane l owns x = 16l..16l+15 (full 512 row per warp).
// Each warp register-rolls an 8-row strip: each row loaded once (+2 halo rows).
// Periodic left/right neighbors come from lane-wrapped __shfl.
// grid = (HH/(ROWS_PER_WARP*WARPS_PER_BLK), BATCH) = (16, 32), block = 128.
__global__ void step_kernel(const float* __restrict__ src, int src_bstride,
                            float* __restrict__ dst, int dst_bstride,
                            const float* __restrict__ Wm,
                            const float* __restrict__ bias,
                            const int* __restrict__ t, int step) {
    const int b    = blockIdx.y;
    const int lane = threadIdx.x & 31;
    const int wid  = threadIdx.x >> 5;

    // --- Derive D, rho from previous-step sums ---
    const float inv = 1.0f / (float)PLANE;
    const float f0 = g_sum0[step * BATCH + b] * inv;
    const float f1 = g_sumc[0 * BATCH + b] * inv;
    const float f2 = g_sumc[1 * BATCH + b] * inv;
    const float f3 = g_sumc[2 * BATCH + b] * inv;
    const float z0 = f0 * Wm[0] + f1 * Wm[2] + f2 * Wm[4] + f3 * Wm[6] + bias[0];
    const float z1 = f0 * Wm[1] + f1 * Wm[3] + f2 * Wm[5] + f3 * Wm[7] + bias[1];
    float D   = D_SCALE   / (1.0f + expf(-z0));
    float rho = RHO_SCALE / (1.0f + expf(-z1));
    if (t[b] <= step) { D = 0.0f; rho = 0.0f; }   // mask off -> exact identity

    const float* __restrict__ u = src + (size_t)b * src_bstride;
    float* __restrict__ v       = dst + (size_t)b * dst_bstride;

    const int strip = blockIdx.x * WARPS_PER_BLK + wid;   // 0..63
    const int y0    = strip * ROWS_PER_WARP;
    const int xoff  = lane << 4;                          // 16 floats per lane

    // rolling rows: r[(i)%3]=prev, r[(i+1)%3]=cur, r[(i+2)%3]=next
    float r[3][16];
    load_row16(r[0], u + ((((y0 + HH - 1) & (HH-1)) << 9) + xoff));
    load_row16(r[1], u + ((y0 << 9) + xoff));

    float ssum = 0.0f;

    #pragma unroll
    for (int i = 0; i < ROWS_PER_WARP; i++) {
        const int y = y0 + i;
        float* prev = r[i % 3];
        float* cur  = r[(i + 1) % 3];
        float* next = r[(i + 2) % 3];
        load_row16(next, u + ((((y + 1) & (HH-1)) << 9) + xoff));

        // periodic left/right across lanes (warp spans the full row)
        const float lft = __shfl_sync(0xffffffffu, cur[15], (lane + 31) & 31);
        const float rgt = __shfl_sync(0xffffffffu, cur[0],  (lane + 1)  & 31);

        float o[16];
        #pragma unroll
        for (int j = 0; j < 16; j++) {
            const float le = (j == 0)  ? lft : cur[j - 1];
            const float ri = (j == 15) ? rgt : cur[j + 1];
            const float lap = prev[j] + next[j] + le + ri - 4.0f * cur[j];
            o[j] = fmaf(D, lap, fmaf(rho * cur[j], 1.0f - cur[j], cur[j]));
            ssum += o[j];
        }

        float4* vo = (float4*)(v + (y << 9) + xoff);
        vo[0] = make_float4(o[0],  o[1],  o[2],  o[3]);
        vo[1] = make_float4(o[4],  o[5],  o[6],  o[7]);
        vo[2] = make_float4(o[8],  o[9],  o[10], o[11]);
        vo[3] = make_float4(o[12], o[13], o[14], o[15]);
    }

    // --- Reduce updated-field sum for next step (one atomic per warp) ---
    #pragma unroll
    for (int o = 16; o > 0; o >>= 1) ssum += __shfl_down_sync(0xffffffffu, ssum, o);
    if (lane == 0) atomicAdd(&g_sum0[(step + 1) * BATCH + b], ssum);
}

extern "C" void kernel_launch(void* const* d_in, const int* in_sizes, int n_in,
                              void* d_out, int out_size) {
    const float* x  = (const float*)d_in[0];   // (32,4,512,512)
    const float* Wm = (const float*)d_in[1];   // (4,2)
    const float* bb = (const float*)d_in[2];   // (2,)
    const int*   t  = (const int*)d_in[3];     // (32,)
    float* out = (float*)d_out;

    zero_sums_kernel<<<1, 320>>>();

    // Copy ch1..3, reduce all per-(b,c) sums.
    init_kernel<<<dim3(PLANE / 4 / 256, BATCH * NCH), dim3(256)>>>(x, out);

    float* bufA; float* bufB;
    cudaGetSymbolAddress((void**)&bufA, g_buf0);
    cudaGetSymbolAddress((void**)&bufB, g_buf1);

    const dim3 sgrid(HH / (ROWS_PER_WARP * WARPS_PER_BLK), BATCH);  // (16, 32)
    const dim3 sblk(WARPS_PER_BLK * 32);                            // 128
    for (int s = 0; s < NSTEPS; s++) {
        const float* src;  int sstride;
        float*       dst;  int dstride;
        if (s == 0) { src = x;  sstride = NCH * PLANE; }           // input ch0
        else        { src = ((s - 1) & 1) ? bufB : bufA; sstride = PLANE; }
        if (s == NSTEPS - 1) { dst = out; dstride = NCH * PLANE; } // output ch0
        else                 { dst = (s & 1) ? bufB : bufA; dstride = PLANE; }
        step_kernel<<<sgrid, sblk>>>(src, sstride, dst, dstride, Wm, bb, t, s);
    }
}

// round 4
// speedup vs baseline: 1.3078x; 1.2890x over previous
#include <cuda_runtime.h>

#define BATCH 32
#define NCH   4
#define HH    512
#define WW    512
#define PLANE (HH*WW)          /* 262144 */
#define NSTEPS 8
#define D_SCALE 0.2f
#define RHO_SCALE 0.1f
#define RPW 4                   /* rows per warp */
#define WPB 8                   /* warps per block */

// Ping-pong scratch for the evolving channel-0 field (2 x 32 MiB).
__device__ float g_buf0[BATCH * PLANE];
__device__ float g_buf1[BATCH * PLANE];
// Per-step channel-0 sums: slot s = sum of field entering step s.
__device__ float g_sum0[(NSTEPS + 1) * BATCH];
// Constant sums of channels 1..3 (index (c-1)*BATCH + b).
__device__ float g_sumc[3 * BATCH];

__global__ void zero_sums_kernel() {
    int i = threadIdx.x;
    if (i < (NSTEPS + 1) * BATCH) g_sum0[i] = 0.0f;
    if (i < 3 * BATCH)            g_sumc[i] = 0.0f;
}

// Copy channels 1..3 input->output, reduce per-(batch,channel) sums.
// grid = (PLANE/4/256, BATCH*NCH), block = 256. Each thread: one float4.
__global__ void init_kernel(const float* __restrict__ x, float* __restrict__ out) {
    const int p = blockIdx.y;            // plane id = b*4 + c
    const int b = p >> 2;
    const int c = p & 3;
    const int i = blockIdx.x * blockDim.x + threadIdx.x;   // 0..65535

    const float4* src = (const float4*)(x + (size_t)p * PLANE);
    float4 v = src[i];
    if (c != 0) {
        ((float4*)(out + (size_t)p * PLANE))[i] = v;
    }
    float s = (v.x + v.y) + (v.z + v.w);

    #pragma unroll
    for (int o = 16; o > 0; o >>= 1) s += __shfl_down_sync(0xffffffffu, s, o);
    __shared__ float ws[8];
    const int lane = threadIdx.x & 31;
    const int w    = threadIdx.x >> 5;
    if (lane == 0) ws[w] = s;
    __syncthreads();
    if (w == 0) {
        s = (lane < 8) ? ws[lane] : 0.0f;
        #pragma unroll
        for (int o = 4; o > 0; o >>= 1) s += __shfl_down_sync(0x000000ffu, s, o);
        if (lane == 0) {
            if (c == 0) atomicAdd(&g_sum0[0 * BATCH + b], s);
            else        atomicAdd(&g_sumc[(c - 1) * BATCH + b], s);
        }
    }
}

// One reaction-diffusion step on channel 0 for all batches.
// Warp-per-row, interleaved layout: lane l, chunk k holds float4 at x = k*128 + l*4.
// Every warp-wide LDG.128/STG.128 is 512B contiguous (4 wavefronts = minimal).
// Horizontal periodic neighbors via lane shuffles; vertical via 4-row register rolling.
// grid = (HH/(RPW*WPB), BATCH) = (16, 32), block = 256.
__global__ __launch_bounds__(256) void step_kernel(
        const float* __restrict__ src, int src_bstride,
        float* __restrict__ dst, int dst_bstride,
        const float* __restrict__ Wm,
        const float* __restrict__ bias,
        const int* __restrict__ t, int step) {
    const int b    = blockIdx.y;
    const int lane = threadIdx.x & 31;
    const int wid  = threadIdx.x >> 5;

    // --- Derive D, rho from previous-step sums ---
    const float inv = 1.0f / (float)PLANE;
    const float f0 = g_sum0[step * BATCH + b] * inv;
    const float f1 = g_sumc[0 * BATCH + b] * inv;
    const float f2 = g_sumc[1 * BATCH + b] * inv;
    const float f3 = g_sumc[2 * BATCH + b] * inv;
    const float z0 = f0 * Wm[0] + f1 * Wm[2] + f2 * Wm[4] + f3 * Wm[6] + bias[0];
    const float z1 = f0 * Wm[1] + f1 * Wm[3] + f2 * Wm[5] + f3 * Wm[7] + bias[1];
    float D   = D_SCALE   / (1.0f + expf(-z0));
    float rho = RHO_SCALE / (1.0f + expf(-z1));
    if (t[b] <= step) { D = 0.0f; rho = 0.0f; }   // mask off -> exact identity

    const float* __restrict__ u = src + (size_t)b * src_bstride;
    float* __restrict__ v       = dst + (size_t)b * dst_bstride;

    const int strip = blockIdx.x * WPB + wid;   // 0..127
    const int y0    = strip * RPW;
    const int xo    = lane << 2;                // float4 slot inside a 128-float chunk

    float4 P[4], C[4], N[4];
    {
        const float* pr = u + (((y0 + HH - 1) & (HH - 1)) << 9);
        const float* cr = u + (y0 << 9);
        #pragma unroll
        for (int k = 0; k < 4; k++) {
            P[k] = *(const float4*)(pr + k * 128 + xo);
            C[k] = *(const float4*)(cr + k * 128 + xo);
        }
    }

    float ssum = 0.0f;

    #pragma unroll
    for (int i = 0; i < RPW; i++) {
        const int y = y0 + i;
        const float* nr = u + ((((y + 1) & (HH - 1)) << 9));
        #pragma unroll
        for (int k = 0; k < 4; k++) N[k] = *(const float4*)(nr + k * 128 + xo);

        // horizontal periodic halos: left of element (k, m=0) and right of (k, m=3)
        float Lk[4], Rk[4];
        #pragma unroll
        for (int k = 0; k < 4; k++) {
            const float lv = (lane == 31) ? C[(k + 3) & 3].w : C[k].w;
            Lk[k] = __shfl_sync(0xffffffffu, lv, (lane + 31) & 31);
            const float rv = (lane == 0) ? C[(k + 1) & 3].x : C[k].x;
            Rk[k] = __shfl_sync(0xffffffffu, rv, (lane + 1) & 31);
        }

        float* vr = v + (y << 9);
        #pragma unroll
        for (int k = 0; k < 4; k++) {
            const float4 cc = C[k], pp = P[k], nn = N[k];
            float4 o;
            o.x = fmaf(D, pp.x + nn.x + Lk[k] + cc.y - 4.0f * cc.x,
                       fmaf(rho * cc.x, 1.0f - cc.x, cc.x));
            o.y = fmaf(D, pp.y + nn.y + cc.x  + cc.z - 4.0f * cc.y,
                       fmaf(rho * cc.y, 1.0f - cc.y, cc.y));
            o.z = fmaf(D, pp.z + nn.z + cc.y  + cc.w - 4.0f * cc.z,
                       fmaf(rho * cc.z, 1.0f - cc.z, cc.z));
            o.w = fmaf(D, pp.w + nn.w + cc.z  + Rk[k] - 4.0f * cc.w,
                       fmaf(rho * cc.w, 1.0f - cc.w, cc.w));
            *(float4*)(vr + k * 128 + xo) = o;
            ssum += (o.x + o.y) + (o.z + o.w);
        }

        #pragma unroll
        for (int k = 0; k < 4; k++) { P[k] = C[k]; C[k] = N[k]; }
    }

    // --- Block-level reduce (all warps in block share batch b), 1 atomic/block ---
    #pragma unroll
    for (int o = 16; o > 0; o >>= 1) ssum += __shfl_down_sync(0xffffffffu, ssum, o);
    __shared__ float ws[WPB];
    if (lane == 0) ws[wid] = ssum;
    __syncthreads();
    if (wid == 0) {
        float s = (lane < WPB) ? ws[lane] : 0.0f;
        #pragma unroll
        for (int o = WPB / 2; o > 0; o >>= 1) s += __shfl_down_sync(0x000000ffu, s, o);
        if (lane == 0) atomicAdd(&g_sum0[(step + 1) * BATCH + b], s);
    }
}

extern "C" void kernel_launch(void* const* d_in, const int* in_sizes, int n_in,
                              void* d_out, int out_size) {
    const float* x  = (const float*)d_in[0];   // (32,4,512,512)
    const float* Wm = (const float*)d_in[1];   // (4,2)
    const float* bb = (const float*)d_in[2];   // (2,)
    const int*   t  = (const int*)d_in[3];     // (32,)
    float* out = (float*)d_out;

    zero_sums_kernel<<<1, 320>>>();

    // Copy ch1..3, reduce all per-(b,c) sums.
    init_kernel<<<dim3(PLANE / 4 / 256, BATCH * NCH), dim3(256)>>>(x, out);

    float* bufA; float* bufB;
    cudaGetSymbolAddress((void**)&bufA, g_buf0);
    cudaGetSymbolAddress((void**)&bufB, g_buf1);

    const dim3 sgrid(HH / (RPW * WPB), BATCH);   // (16, 32)
    const dim3 sblk(WPB * 32);                   // 256
    for (int s = 0; s < NSTEPS; s++) {
        const float* src;  int sstride;
        float*       dst;  int dstride;
        if (s == 0) { src = x;  sstride = NCH * PLANE; }           // input ch0
        else        { src = ((s - 1) & 1) ? bufB : bufA; sstride = PLANE; }
        if (s == NSTEPS - 1) { dst = out; dstride = NCH * PLANE; } // output ch0
        else                 { dst = (s & 1) ? bufB : bufA; dstride = PLANE; }
        step_kernel<<<sgrid, sblk>>>(src, sstride, dst, dstride, Wm, bb, t, s);
    }
}

// round 5
// speedup vs baseline: 1.3302x; 1.0171x over previous
#include <cuda_runtime.h>

#define BATCH 32
#define NCH   4
#define HH    512
#define WW    512
#define PLANE (HH*WW)          /* 262144 */
#define NSTEPS 8
#define D_SCALE 0.2f
#define RHO_SCALE 0.1f
#define RPW 8                   /* rows per warp */
#define WPB 8                   /* warps per block */

// Ping-pong scratch for the evolving channel-0 field (2 x 32 MiB).
__device__ float g_buf0[BATCH * PLANE];
__device__ float g_buf1[BATCH * PLANE];
// Per-step channel-0 sums: slot s = sum of field entering step s.
__device__ float g_sum0[(NSTEPS + 1) * BATCH];
// Constant sums of channels 1..3 (index (c-1)*BATCH + b).
__device__ float g_sumc[3 * BATCH];

__global__ void zero_sums_kernel() {
    int i = threadIdx.x;
    if (i < (NSTEPS + 1) * BATCH) g_sum0[i] = 0.0f;
    if (i < 3 * BATCH)            g_sumc[i] = 0.0f;
}

// Copy channels 1..3 input->output, reduce per-(batch,channel) sums.
// grid = (PLANE/4/256, BATCH*NCH), block = 256. Each thread: one float4.
__global__ void init_kernel(const float* __restrict__ x, float* __restrict__ out) {
    const int p = blockIdx.y;            // plane id = b*4 + c
    const int b = p >> 2;
    const int c = p & 3;
    const int i = blockIdx.x * blockDim.x + threadIdx.x;   // 0..65535

    const float4* src = (const float4*)(x + (size_t)p * PLANE);
    float4 v = src[i];
    if (c != 0) {
        ((float4*)(out + (size_t)p * PLANE))[i] = v;
    }
    float s = (v.x + v.y) + (v.z + v.w);

    #pragma unroll
    for (int o = 16; o > 0; o >>= 1) s += __shfl_down_sync(0xffffffffu, s, o);
    __shared__ float ws[8];
    const int lane = threadIdx.x & 31;
    const int w    = threadIdx.x >> 5;
    if (lane == 0) ws[w] = s;
    __syncthreads();
    if (w == 0) {
        s = (lane < 8) ? ws[lane] : 0.0f;
        #pragma unroll
        for (int o = 4; o > 0; o >>= 1) s += __shfl_down_sync(0x000000ffu, s, o);
        if (lane == 0) {
            if (c == 0) atomicAdd(&g_sum0[0 * BATCH + b], s);
            else        atomicAdd(&g_sumc[(c - 1) * BATCH + b], s);
        }
    }
}

// One reaction-diffusion step on channel 0 for all batches.
// Warp owns a 128-float column chunk (1 float4/lane), register-rolls RPW rows.
// Rolling window = 3 float4 = 12 regs -> high occupancy, each row read once
// (+2 halo rows per strip). Horizontal neighbors: shfl for interior, 2
// predicated scalar loads (lanes 0/31) for the periodic chunk edges.
// Warp id w = blockIdx.x*WPB+wid: chunk = w&3, strip = w>>2.
// grid = (4*HH/RPW/WPB, BATCH) = (32, 32), block = 256.
__global__ __launch_bounds__(256) void step_kernel(
        const float* __restrict__ src, int src_bstride,
        float* __restrict__ dst, int dst_bstride,
        const float* __restrict__ Wm,
        const float* __restrict__ bias,
        const int* __restrict__ t, int step) {
    const int b    = blockIdx.y;
    const int lane = threadIdx.x & 31;
    const int wid  = threadIdx.x >> 5;

    // --- Derive D, rho from previous-step sums ---
    const float inv = 1.0f / (float)PLANE;
    const float f0 = g_sum0[step * BATCH + b] * inv;
    const float f1 = g_sumc[0 * BATCH + b] * inv;
    const float f2 = g_sumc[1 * BATCH + b] * inv;
    const float f3 = g_sumc[2 * BATCH + b] * inv;
    const float z0 = f0 * Wm[0] + f1 * Wm[2] + f2 * Wm[4] + f3 * Wm[6] + bias[0];
    const float z1 = f0 * Wm[1] + f1 * Wm[3] + f2 * Wm[5] + f3 * Wm[7] + bias[1];
    float D   = D_SCALE   / (1.0f + expf(-z0));
    float rho = RHO_SCALE / (1.0f + expf(-z1));
    if (t[b] <= step) { D = 0.0f; rho = 0.0f; }   // mask off -> exact identity

    const float* __restrict__ u = src + (size_t)b * src_bstride;
    float* __restrict__ v       = dst + (size_t)b * dst_bstride;

    const int w     = blockIdx.x * WPB + wid;   // 0..255
    const int chunk = w & 3;                    // x chunk (128 floats)
    const int strip = w >> 2;                   // 0..63
    const int y0    = strip * RPW;
    const int xb    = chunk << 7;               // chunk base x
    const int x4    = xb + (lane << 2);         // this lane's float4 x
    const int xl    = (xb + WW - 1) & (WW - 1); // periodic left-edge x
    const int xr    = (xb + 128) & (WW - 1);    // periodic right-edge x

    float4 P = *(const float4*)(u + (((y0 + HH - 1) & (HH - 1)) << 9) + x4);
    float4 C = *(const float4*)(u + (y0 << 9) + x4);
    float4 N = *(const float4*)(u + (((y0 + 1) & (HH - 1)) << 9) + x4);

    float ssum = 0.0f;

    #pragma unroll
    for (int i = 0; i < RPW; i++) {
        const int y   = y0 + i;
        const int row = y << 9;

        // prefetch next row (address-only dependency -> overlaps compute)
        float4 N2;
        if (i < RPW - 1)
            N2 = *(const float4*)(u + (((y + 2) & (HH - 1)) << 9) + x4);

        // periodic horizontal neighbors
        float le = __shfl_up_sync(0xffffffffu, C.w, 1);
        float ri = __shfl_down_sync(0xffffffffu, C.x, 1);
        if (lane == 0)  le = u[row + xl];
        if (lane == 31) ri = u[row + xr];

        float4 o;
        o.x = fmaf(D, P.x + N.x + le  + C.y - 4.0f * C.x, fmaf(rho * C.x, 1.0f - C.x, C.x));
        o.y = fmaf(D, P.y + N.y + C.x + C.z - 4.0f * C.y, fmaf(rho * C.y, 1.0f - C.y, C.y));
        o.z = fmaf(D, P.z + N.z + C.y + C.w - 4.0f * C.z, fmaf(rho * C.z, 1.0f - C.z, C.z));
        o.w = fmaf(D, P.w + N.w + C.z + ri  - 4.0f * C.w, fmaf(rho * C.w, 1.0f - C.w, C.w));

        *(float4*)(v + row + x4) = o;
        ssum += (o.x + o.y) + (o.z + o.w);

        P = C; C = N; N = N2;
    }

    // --- Block-level reduce (all warps in block share batch b), 1 atomic/block ---
    #pragma unroll
    for (int o = 16; o > 0; o >>= 1) ssum += __shfl_down_sync(0xffffffffu, ssum, o);
    __shared__ float ws[WPB];
    if (lane == 0) ws[wid] = ssum;
    __syncthreads();
    if (wid == 0) {
        float s = (lane < WPB) ? ws[lane] : 0.0f;
        #pragma unroll
        for (int o = WPB / 2; o > 0; o >>= 1) s += __shfl_down_sync(0x000000ffu, s, o);
        if (lane == 0) atomicAdd(&g_sum0[(step + 1) * BATCH + b], s);
    }
}

extern "C" void kernel_launch(void* const* d_in, const int* in_sizes, int n_in,
                              void* d_out, int out_size) {
    const float* x  = (const float*)d_in[0];   // (32,4,512,512)
    const float* Wm = (const float*)d_in[1];   // (4,2)
    const float* bb = (const float*)d_in[2];   // (2,)
    const int*   t  = (const int*)d_in[3];     // (32,)
    float* out = (float*)d_out;

    zero_sums_kernel<<<1, 320>>>();

    // Copy ch1..3, reduce all per-(b,c) sums.
    init_kernel<<<dim3(PLANE / 4 / 256, BATCH * NCH), dim3(256)>>>(x, out);

    float* bufA; float* bufB;
    cudaGetSymbolAddress((void**)&bufA, g_buf0);
    cudaGetSymbolAddress((void**)&bufB, g_buf1);

    const dim3 sgrid(4 * HH / RPW / WPB, BATCH);   // (32, 32)
    const dim3 sblk(WPB * 32);                     // 256
    for (int s = 0; s < NSTEPS; s++) {
        const float* src;  int sstride;
        float*       dst;  int dstride;
        if (s == 0) { src = x;  sstride = NCH * PLANE; }           // input ch0
        else        { src = ((s - 1) & 1) ? bufB : bufA; sstride = PLANE; }
        if (s == NSTEPS - 1) { dst = out; dstride = NCH * PLANE; } // output ch0
        else                 { dst = (s & 1) ? bufB : bufA; dstride = PLANE; }
        step_kernel<<<sgrid, sblk>>>(src, sstride, dst, dstride, Wm, bb, t, s);
    }
}